// round 14
// baseline (speedup 1.0000x reference)
#include <cuda_runtime.h>
#include <math.h>

#define NB 64      // batch
#define NT 1024    // seq len
#define ND 256     // input dim
#define NH 1024    // hidden
#define NC 1000    // classes
#define RCTAS 128  // recurrence CTAs
#define WORKERS 20 // xproj worker CTAs (spare SMs)
#define NTILES (NT * 16)

typedef unsigned long long u64;

// ---------------- scratch (device globals) ----------------
// g_z[t] = xproj_t (written by worker CTAs) + red-accumulated W_hh*h_{t-1}.
// h = modrelu(z) computed on the fly by readers.
__device__ float g_z[NT * NH * NB];        // [t][n][b]  256 MB
__device__ float g_xT[NT * ND * NB];       // [t][d][b]
__device__ float g_wihT[ND * NH];          // [d][n]
__device__ unsigned g_arr[16];             // per n-group(64) chain arrival counters
__device__ unsigned g_xarr[NT];            // per-t xproj tile counters (16 each)

// ---------------- sync / math primitives ----------------
__device__ __forceinline__ unsigned ld_acq(const unsigned* p) {
    unsigned v;
    asm volatile("ld.global.acquire.gpu.u32 %0, [%1];" : "=r"(v) : "l"(p));
    return v;
}
#define FMA2(d, a, b) asm("fma.rn.f32x2 %0, %1, %2, %0;" : "+l"(d) : "l"(a), "l"(b))
__device__ __forceinline__ float lo32(u64 v) { return __uint_as_float((unsigned)v); }
__device__ __forceinline__ float hi32(u64 v) { return __uint_as_float((unsigned)(v >> 32)); }

__device__ __forceinline__ void red_add_v4(float* p, float v0, float v1, float v2, float v3) {
    asm volatile("red.global.add.v4.f32 [%0], {%1, %2, %3, %4};"
                 :: "l"(p), "f"(v0), "f"(v1), "f"(v2), "f"(v3) : "memory");
}
__device__ __forceinline__ float modrelu(float z, float bm) {
    float a = fabsf(z) + bm;
    return (a > 0.0f) ? copysignf(a, z) : 0.0f;
}

// ---------------- init: reset counters each launch ----------------
__global__ void init_kernel() {
    int i = blockIdx.x * 256 + threadIdx.x;
    if (i < NT) g_xarr[i] = 0u;
    if (blockIdx.x == 0 && threadIdx.x < 16) g_arr[threadIdx.x] = 0u;
}

// ---------------- transpose kernels (R7, unchanged) ----------------
__global__ __launch_bounds__(256) void xpose_kernel(const float* __restrict__ x) {
    __shared__ float T[64][65];
    const int t0 = blockIdx.x;
    const int d0 = blockIdx.y * 64;
    const int tid = threadIdx.x;
    const int b = tid & 63;
    #pragma unroll
    for (int it = 0; it < 4; it++) {
        int d4 = (tid >> 6) * 4 + it * 16;
        float4 v = __ldg((const float4*)(x + (long)b * (NT * ND) + (long)t0 * ND + d0 + d4));
        T[d4 + 0][b] = v.x; T[d4 + 1][b] = v.y;
        T[d4 + 2][b] = v.z; T[d4 + 3][b] = v.w;
    }
    __syncthreads();
    #pragma unroll
    for (int it = 0; it < 4; it++) {
        int dr = it * 16 + (tid >> 4);
        int b4 = (tid & 15) * 4;
        float4 v = make_float4(T[dr][b4], T[dr][b4 + 1], T[dr][b4 + 2], T[dr][b4 + 3]);
        *(float4*)(g_xT + ((long)t0 * ND + d0 + dr) * NB + b4) = v;
    }
}

__global__ __launch_bounds__(256) void wpose_kernel(const float* __restrict__ w_ih) {
    __shared__ float T[64][65];
    const int n0 = blockIdx.x * 64;
    const int d0 = blockIdx.y * 64;
    const int tid = threadIdx.x;
    const int n = tid & 63;
    #pragma unroll
    for (int it = 0; it < 4; it++) {
        int d4 = (tid >> 6) * 4 + it * 16;
        float4 v = __ldg((const float4*)(w_ih + (long)(n0 + n) * ND + d0 + d4));
        T[d4 + 0][n] = v.x; T[d4 + 1][n] = v.y;
        T[d4 + 2][n] = v.z; T[d4 + 3][n] = v.w;
    }
    __syncthreads();
    #pragma unroll
    for (int it = 0; it < 4; it++) {
        int dr = it * 16 + (tid >> 4);
        int n4 = (tid & 15) * 4;
        float4 v = make_float4(T[dr][n4], T[dr][n4 + 1], T[dr][n4 + 2], T[dr][n4 + 3]);
        *(float4*)(g_wihT + (long)(d0 + dr) * NH + n0 + n4) = v;
    }
}

// ---------------- xproj tile body (R13-proven), used by worker CTAs ----------------
__device__ __forceinline__ void xproj_tile(int t0, int n0, float* As_dup, float* Bs) {
    const int tid = threadIdx.x;
    const int tx = tid & 15, ty = tid >> 4;

    u64 acc[4][2];
    #pragma unroll
    for (int i = 0; i < 4; i++) { acc[i][0] = 0ull; acc[i][1] = 0ull; }

    for (int p = 0; p < 4; p++) {
        __syncthreads();
        {
            const float2* xsrc = (const float2*)(g_xT + ((long)t0 * ND + p * 64) * NB);
            float4* Ad4 = (float4*)As_dup;
            #pragma unroll
            for (int it = 0; it < 8; it++) {
                int f2 = it * 256 + tid;
                float2 v = __ldg(&xsrc[f2]);
                Ad4[f2] = make_float4(v.x, v.x, v.y, v.y);
            }
        }
        {
            const float4* wsrc = (const float4*)(g_wihT + (long)(p * 64) * NH + n0);
            #pragma unroll
            for (int it = 0; it < 4; it++) {
                int f4 = it * 256 + tid;
                int k = f4 >> 4, n4 = f4 & 15;
                ((float4*)Bs)[f4] = __ldg(&wsrc[(long)k * (NH / 4) + n4]);
            }
        }
        __syncthreads();

        #pragma unroll 8
        for (int kk = 0; kk < 64; kk++) {
            const ulonglong2 bp  = *(const ulonglong2*)(Bs + kk * 64 + tx * 4);
            const ulonglong2 a01 = *(const ulonglong2*)(As_dup + kk * 128 + ty * 8);
            const ulonglong2 a23 = *(const ulonglong2*)(As_dup + kk * 128 + ty * 8 + 4);
            FMA2(acc[0][0], a01.x, bp.x); FMA2(acc[0][1], a01.x, bp.y);
            FMA2(acc[1][0], a01.y, bp.x); FMA2(acc[1][1], a01.y, bp.y);
            FMA2(acc[2][0], a23.x, bp.x); FMA2(acc[2][1], a23.x, bp.y);
            FMA2(acc[3][0], a23.y, bp.x); FMA2(acc[3][1], a23.y, bp.y);
        }
    }

    #pragma unroll
    for (int j = 0; j < 4; j++) {
        int jp = j >> 1;
        float4 v;
        if (j & 1) v = make_float4(hi32(acc[0][jp]), hi32(acc[1][jp]),
                                   hi32(acc[2][jp]), hi32(acc[3][jp]));
        else       v = make_float4(lo32(acc[0][jp]), lo32(acc[1][jp]),
                                   lo32(acc[2][jp]), lo32(acc[3][jp]));
        *(float4*)(g_z + ((long)t0 * NH + n0 + tx * 4 + j) * NB + ty * 4) = v;
    }
}

// ---------------- fused persistent kernel ----------------
// bids 0..127  : recurrence chain (R13 body + xarr polls)
// bids 128..147: xproj workers (tile stream tau = bid-128, +20, ... t-major)
__global__ __launch_bounds__(256) void main_kernel(
    const float* __restrict__ w_hh, const float* __restrict__ b_mod)
{
    extern __shared__ float sm[];
    const int tid = threadIdx.x;
    const int cta = blockIdx.x;

    if (cta >= RCTAS) {
        // ================= xproj worker =================
        float* As_dup = sm;              // 32 KB
        float* Bs = sm + 64 * 128;       // 16 KB
        for (int tau = cta - RCTAS; tau < NTILES; tau += WORKERS) {
            int t0 = tau >> 4, nb = tau & 15;
            xproj_tile(t0, nb * 64, As_dup, Bs);
            __syncthreads();             // all STGs of this tile issued
            if (tid == 0) {
                __threadfence();
                atomicAdd(&g_xarr[t0], 1u);
            }
        }
        return;
    }

    // ================= recurrence chain (R13) =================
    float* Wd = sm;                       // [128k][128] dup W, 64 KB
    float* As = sm + 128 * 128;           // [128k][64b] natural h, 32 KB
    __shared__ float s_bm[128];

    const int nc = cta & 15;
    const int kc = cta >> 4;
    const int tn = tid >> 4;              // n-quad 0..15
    const int tb = tid & 15;              // b-quad 0..15

    // one-time: W slice dup into persistent smem
    #pragma unroll
    for (int it = 0; it < 8; it++) {
        int f4 = it * 256 + tid;
        int np = f4 >> 5, k0 = (f4 & 31) * 4;
        float4 w = __ldg((const float4*)(w_hh + (long)(nc * 64 + np) * NH + kc * 128 + k0));
        *(float2*)(Wd + (k0 + 0) * 128 + 2 * np) = make_float2(w.x, w.x);
        *(float2*)(Wd + (k0 + 1) * 128 + 2 * np) = make_float2(w.y, w.y);
        *(float2*)(Wd + (k0 + 2) * 128 + 2 * np) = make_float2(w.z, w.z);
        *(float2*)(Wd + (k0 + 3) * 128 + 2 * np) = make_float2(w.w, w.w);
    }
    if (tid < 128) s_bm[tid] = __ldg(&b_mod[kc * 128 + tid]);
    __syncthreads();

    for (int t = 1; t < NT; t++) {
        // ---- wait: chain flags + xproj readiness ----
        if (t > 1) {
            unsigned target = (unsigned)(8 * (t - 1));
            if (tid == 0)  while (ld_acq(&g_arr[2 * kc]) < target) {}
            if (tid == 32) while (ld_acq(&g_arr[2 * kc + 1]) < target) {}
        }
        if (tid == 64) while (ld_acq(&g_xarr[t]) < 16u) {}       // red target ready
        if (tid == 96 && t == 1) while (ld_acq(&g_xarr[0]) < 16u) {} // stage source (t=1)
        __syncthreads();

        // ---- stage: As[k][b] = modrelu(z_{t-1}[kc*128+k][b]) ----
        {
            const float* zsrc = g_z + ((long)(t - 1) * NH + kc * 128) * NB;
            #pragma unroll
            for (int i = 0; i < 8; i++) {
                int f = i * 256 + tid;            // 2048 f4 = 128k x 16
                int k = f >> 4, c = f & 15;
                float4 z = __ldcg((const float4*)(zsrc + (long)k * NB + c * 4));
                float bm = s_bm[k];
                float4 h;
                h.x = modrelu(z.x, bm); h.y = modrelu(z.y, bm);
                h.z = modrelu(z.z, bm); h.w = modrelu(z.w, bm);
                *(float4*)(As + k * 64 + c * 4) = h;
            }
        }
        __syncthreads();

        // ---- GEMM: 64n x 64b x 128k, 3 LDS.128 + 8 FFMA2 per kk ----
        u64 acc[4][2];
        #pragma unroll
        for (int i = 0; i < 4; i++) { acc[i][0] = 0ull; acc[i][1] = 0ull; }

        #pragma unroll 8
        for (int kk = 0; kk < 128; kk++) {
            const ulonglong2 a   = *(const ulonglong2*)(As + kk * 64 + tb * 4);
            const ulonglong2 w01 = *(const ulonglong2*)(Wd + kk * 128 + tn * 8);
            const ulonglong2 w23 = *(const ulonglong2*)(Wd + kk * 128 + tn * 8 + 4);
            FMA2(acc[0][0], a.x, w01.x); FMA2(acc[0][1], a.y, w01.x);
            FMA2(acc[1][0], a.x, w01.y); FMA2(acc[1][1], a.y, w01.y);
            FMA2(acc[2][0], a.x, w23.x); FMA2(acc[2][1], a.y, w23.x);
            FMA2(acc[3][0], a.x, w23.y); FMA2(acc[3][1], a.y, w23.y);
        }

        // ---- red-accumulate into z_t ----
        {
            float* zdst = g_z + ((long)t * NH + nc * 64 + 4 * tn) * NB + 4 * tb;
            #pragma unroll
            for (int j = 0; j < 4; j++)
                red_add_v4(zdst + (long)j * NB,
                           lo32(acc[j][0]), hi32(acc[j][0]),
                           lo32(acc[j][1]), hi32(acc[j][1]));
        }

        // ---- arrive ----
        __syncthreads();
        if (tid == 0) {
            __threadfence();
            atomicAdd(&g_arr[nc], 1u);
        }
    }
}

// ---------------- kernel 3: fc head (R7, unchanged) ----------------
__global__ __launch_bounds__(256) void fc_kernel(
    const float* __restrict__ w_fc, const float* __restrict__ b_fc,
    const float* __restrict__ b_mod, float* __restrict__ out)
{
    __shared__ float As[64][64];   // [k][b] = h_last slab
    __shared__ float Bs[64][64];   // [k][c']
    const int n0 = blockIdx.x * 64;
    const int tid = threadIdx.x;
    const int tx = tid & 15, ty = tid >> 4;
    const float* zlast = g_z + (long)(NT - 1) * NH * NB;
    float acc[4][4] = {};

    for (int s = 0; s < 16; s++) {
        __syncthreads();
        #pragma unroll
        for (int it = 0; it < 4; it++) {
            int f4 = it * 256 + tid;
            int n = s * 64 + (f4 >> 4);
            float4 z = __ldcg((const float4*)zlast + s * 1024 + f4);
            float bm = __ldg(&b_mod[n]);
            float4 h;
            h.x = modrelu(z.x, bm); h.y = modrelu(z.y, bm);
            h.z = modrelu(z.z, bm); h.w = modrelu(z.w, bm);
            ((float4*)As)[f4] = h;
        }
        #pragma unroll
        for (int it = 0; it < 4; it++) {
            int f4 = it * 256 + tid;
            int np = f4 >> 4, k0 = (f4 & 15) * 4;
            int row = n0 + np; if (row >= NC) row = NC - 1;
            float4 w = *(const float4*)(w_fc + (long)row * NH + s * 64 + k0);
            Bs[k0 + 0][np] = w.x; Bs[k0 + 1][np] = w.y;
            Bs[k0 + 2][np] = w.z; Bs[k0 + 3][np] = w.w;
        }
        __syncthreads();
        #pragma unroll 8
        for (int kk = 0; kk < 64; kk++) {
            float4 av = *(const float4*)(&As[kk][ty * 4]);
            float4 bv = *(const float4*)(&Bs[kk][tx * 4]);
            float a[4] = {av.x, av.y, av.z, av.w};
            float b[4] = {bv.x, bv.y, bv.z, bv.w};
            #pragma unroll
            for (int i = 0; i < 4; i++)
                #pragma unroll
                for (int j = 0; j < 4; j++)
                    acc[i][j] += a[i] * b[j];
        }
    }
    #pragma unroll
    for (int i = 0; i < 4; i++) {
        #pragma unroll
        for (int j = 0; j < 4; j++) {
            int c = n0 + tx * 4 + j;
            if (c < NC) out[(long)(ty * 4 + i) * NC + c] = acc[i][j] + __ldg(&b_fc[c]);
        }
    }
}

// ---------------- launch ----------------
extern "C" void kernel_launch(void* const* d_in, const int* in_sizes, int n_in,
                              void* d_out, int out_size)
{
    const float* x     = (const float*)d_in[0];  // [64,1024,256]
    const float* w_ih  = (const float*)d_in[1];  // [1024,256]
    const float* w_hh  = (const float*)d_in[2];  // [1024,1024]
    const float* b_mod = (const float*)d_in[3];  // [1024]
    const float* w_fc  = (const float*)d_in[4];  // [1000,1024]
    const float* b_fc  = (const float*)d_in[5];  // [1000]
    float* out = (float*)d_out;                  // [64,1000]

    cudaFuncSetAttribute(main_kernel, cudaFuncAttributeMaxDynamicSharedMemorySize, 98304);

    init_kernel<<<4, 256>>>();
    xpose_kernel<<<dim3(NT, ND / 64), 256>>>(x);
    wpose_kernel<<<dim3(NH / 64, ND / 64), 256>>>(w_ih);
    main_kernel<<<RCTAS + WORKERS, 256, 98304>>>(w_hh, b_mod);
    fc_kernel<<<(NC + 63) / 64, 256>>>(w_fc, b_fc, b_mod, out);
}

// round 15
// speedup vs baseline: 1.0820x; 1.0820x over previous
#include <cuda_runtime.h>
#include <math.h>

#define NB 64      // batch
#define NT 1024    // seq len
#define ND 256     // input dim
#define NH 1024    // hidden
#define NC 1000    // classes
#define RCTAS 128  // recurrence CTAs
#define WORKERS 20 // xproj worker CTAs (spare SMs)
#define NTILES (NT * 16)

typedef unsigned long long u64;

// ---------------- scratch (device globals) ----------------
// g_z[t] = xproj_t (written by worker CTAs) + red-accumulated W_hh*h_{t-1}.
// h = modrelu(z) computed on the fly by readers.
__device__ float g_z[NT * NH * NB];        // [t][n][b]  256 MB
__device__ float g_xT[NT * ND * NB];       // [t][d][b]
__device__ float g_wihT[ND * NH];          // [d][n]
__device__ unsigned g_arr[16];             // per n-group(64) chain arrival counters
__device__ unsigned g_xarr[NT];            // per-t xproj tile counters (16 each)

// ---------------- sync / math primitives ----------------
__device__ __forceinline__ unsigned ld_acq(const unsigned* p) {
    unsigned v;
    asm volatile("ld.global.acquire.gpu.u32 %0, [%1];" : "=r"(v) : "l"(p));
    return v;
}
#define FMA2(d, a, b) asm("fma.rn.f32x2 %0, %1, %2, %0;" : "+l"(d) : "l"(a), "l"(b))
__device__ __forceinline__ float lo32(u64 v) { return __uint_as_float((unsigned)v); }
__device__ __forceinline__ float hi32(u64 v) { return __uint_as_float((unsigned)(v >> 32)); }

__device__ __forceinline__ void red_add_v4(float* p, float v0, float v1, float v2, float v3) {
    asm volatile("red.global.add.v4.f32 [%0], {%1, %2, %3, %4};"
                 :: "l"(p), "f"(v0), "f"(v1), "f"(v2), "f"(v3) : "memory");
}
__device__ __forceinline__ float modrelu(float z, float bm) {
    float a = fabsf(z) + bm;
    return (a > 0.0f) ? copysignf(a, z) : 0.0f;
}

// ---------------- init: reset counters each launch ----------------
__global__ void init_kernel() {
    int i = blockIdx.x * 256 + threadIdx.x;
    if (i < NT) g_xarr[i] = 0u;
    if (blockIdx.x == 0 && threadIdx.x < 16) g_arr[threadIdx.x] = 0u;
}

// ---------------- transpose kernels (R7, unchanged) ----------------
__global__ __launch_bounds__(256) void xpose_kernel(const float* __restrict__ x) {
    __shared__ float T[64][65];
    const int t0 = blockIdx.x;
    const int d0 = blockIdx.y * 64;
    const int tid = threadIdx.x;
    const int b = tid & 63;
    #pragma unroll
    for (int it = 0; it < 4; it++) {
        int d4 = (tid >> 6) * 4 + it * 16;
        float4 v = __ldg((const float4*)(x + (long)b * (NT * ND) + (long)t0 * ND + d0 + d4));
        T[d4 + 0][b] = v.x; T[d4 + 1][b] = v.y;
        T[d4 + 2][b] = v.z; T[d4 + 3][b] = v.w;
    }
    __syncthreads();
    #pragma unroll
    for (int it = 0; it < 4; it++) {
        int dr = it * 16 + (tid >> 4);
        int b4 = (tid & 15) * 4;
        float4 v = make_float4(T[dr][b4], T[dr][b4 + 1], T[dr][b4 + 2], T[dr][b4 + 3]);
        *(float4*)(g_xT + ((long)t0 * ND + d0 + dr) * NB + b4) = v;
    }
}

__global__ __launch_bounds__(256) void wpose_kernel(const float* __restrict__ w_ih) {
    __shared__ float T[64][65];
    const int n0 = blockIdx.x * 64;
    const int d0 = blockIdx.y * 64;
    const int tid = threadIdx.x;
    const int n = tid & 63;
    #pragma unroll
    for (int it = 0; it < 4; it++) {
        int d4 = (tid >> 6) * 4 + it * 16;
        float4 v = __ldg((const float4*)(w_ih + (long)(n0 + n) * ND + d0 + d4));
        T[d4 + 0][n] = v.x; T[d4 + 1][n] = v.y;
        T[d4 + 2][n] = v.z; T[d4 + 3][n] = v.w;
    }
    __syncthreads();
    #pragma unroll
    for (int it = 0; it < 4; it++) {
        int dr = it * 16 + (tid >> 4);
        int n4 = (tid & 15) * 4;
        float4 v = make_float4(T[dr][n4], T[dr][n4 + 1], T[dr][n4 + 2], T[dr][n4 + 3]);
        *(float4*)(g_wihT + (long)(d0 + dr) * NH + n0 + n4) = v;
    }
}

// ---------------- fused persistent kernel ----------------
// bids 0..127  : recurrence chain (R13 body + xarr polls; proven)
// bids 128..147: xproj workers, register-prefetch double-buffered pipeline
__global__ __launch_bounds__(256) void main_kernel(
    const float* __restrict__ w_hh, const float* __restrict__ b_mod)
{
    extern __shared__ float sm[];
    const int tid = threadIdx.x;
    const int cta = blockIdx.x;

    if (cta >= RCTAS) {
        // ================= xproj worker (pipelined) =================
        // smem: Ab[2] 32 KB each (dup-A [64k][128]), Bb[2] 16 KB each ([64k][64])
        float* Ab[2] = { sm, sm + 8192 };
        float* Bb[2] = { sm + 16384, sm + 20480 };
        const int tx = tid & 15, ty = tid >> 4;

        float2 ra[8];
        float4 rb[4];

        for (int tau = cta - RCTAS; tau < NTILES; tau += WORKERS) {
            const int t0 = tau >> 4;
            const int n0 = (tau & 15) * 64;

            // ---- LDG pass p into registers ----
            #define W_LDG(p)                                                          \
                {                                                                     \
                    const float2* xs = (const float2*)(g_xT +                         \
                                        ((long)t0 * ND + (p) * 64) * NB);             \
                    _Pragma("unroll")                                                 \
                    for (int it = 0; it < 8; it++) ra[it] = __ldg(&xs[it * 256 + tid]);\
                    const float4* ws = (const float4*)(g_wihT +                       \
                                        (long)((p) * 64) * NH + n0);                  \
                    _Pragma("unroll")                                                 \
                    for (int it = 0; it < 4; it++) {                                  \
                        int f4 = it * 256 + tid;                                      \
                        rb[it] = __ldg(&ws[(long)(f4 >> 4) * (NH / 4) + (f4 & 15)]);  \
                    }                                                                 \
                }
            // ---- STS registers into buffer bi ----
            #define W_STS(bi)                                                         \
                {                                                                     \
                    float4* Ad4 = (float4*)Ab[bi];                                    \
                    _Pragma("unroll")                                                 \
                    for (int it = 0; it < 8; it++) {                                  \
                        float2 v = ra[it];                                            \
                        Ad4[it * 256 + tid] = make_float4(v.x, v.x, v.y, v.y);        \
                    }                                                                 \
                    float4* B4 = (float4*)Bb[bi];                                     \
                    _Pragma("unroll")                                                 \
                    for (int it = 0; it < 4; it++) B4[it * 256 + tid] = rb[it];       \
                }

            u64 acc[4][2];
            #pragma unroll
            for (int i = 0; i < 4; i++) { acc[i][0] = 0ull; acc[i][1] = 0ull; }

            // prologue
            W_LDG(0)
            W_STS(0)
            __syncthreads();

            #pragma unroll
            for (int p = 0; p < 4; p++) {
                if (p < 3) W_LDG(p + 1)          // prefetch under FFMA
                float* As_dup = Ab[p & 1];
                float* Bs = Bb[p & 1];
                #pragma unroll 8
                for (int kk = 0; kk < 64; kk++) {
                    const ulonglong2 bp  = *(const ulonglong2*)(Bs + kk * 64 + tx * 4);
                    const ulonglong2 a01 = *(const ulonglong2*)(As_dup + kk * 128 + ty * 8);
                    const ulonglong2 a23 = *(const ulonglong2*)(As_dup + kk * 128 + ty * 8 + 4);
                    FMA2(acc[0][0], a01.x, bp.x); FMA2(acc[0][1], a01.x, bp.y);
                    FMA2(acc[1][0], a01.y, bp.x); FMA2(acc[1][1], a01.y, bp.y);
                    FMA2(acc[2][0], a23.x, bp.x); FMA2(acc[2][1], a23.x, bp.y);
                    FMA2(acc[3][0], a23.y, bp.x); FMA2(acc[3][1], a23.y, bp.y);
                }
                if (p < 3) {
                    W_STS((p + 1) & 1)           // other buffer; prev reader done 2 syncs ago
                    __syncthreads();
                }
            }

            // epilogue: store tile to g_z[t0]
            #pragma unroll
            for (int j = 0; j < 4; j++) {
                int jp = j >> 1;
                float4 v;
                if (j & 1) v = make_float4(hi32(acc[0][jp]), hi32(acc[1][jp]),
                                           hi32(acc[2][jp]), hi32(acc[3][jp]));
                else       v = make_float4(lo32(acc[0][jp]), lo32(acc[1][jp]),
                                           lo32(acc[2][jp]), lo32(acc[3][jp]));
                *(float4*)(g_z + ((long)t0 * NH + n0 + tx * 4 + j) * NB + ty * 4) = v;
            }
            __syncthreads();                     // all STGs issued; also guards buf reuse
            if (tid == 0) {
                __threadfence();
                atomicAdd(&g_xarr[t0], 1u);
            }
            #undef W_LDG
            #undef W_STS
        }
        return;
    }

    // ================= recurrence chain (R13 body, proven) =================
    float* Wd = sm;                       // [128k][128] dup W, 64 KB
    float* As = sm + 128 * 128;           // [128k][64b] natural h, 32 KB
    __shared__ float s_bm[128];

    const int nc = cta & 15;
    const int kc = cta >> 4;
    const int tn = tid >> 4;              // n-quad 0..15
    const int tb = tid & 15;              // b-quad 0..15

    // one-time: W slice dup into persistent smem
    #pragma unroll
    for (int it = 0; it < 8; it++) {
        int f4 = it * 256 + tid;
        int np = f4 >> 5, k0 = (f4 & 31) * 4;
        float4 w = __ldg((const float4*)(w_hh + (long)(nc * 64 + np) * NH + kc * 128 + k0));
        *(float2*)(Wd + (k0 + 0) * 128 + 2 * np) = make_float2(w.x, w.x);
        *(float2*)(Wd + (k0 + 1) * 128 + 2 * np) = make_float2(w.y, w.y);
        *(float2*)(Wd + (k0 + 2) * 128 + 2 * np) = make_float2(w.z, w.z);
        *(float2*)(Wd + (k0 + 3) * 128 + 2 * np) = make_float2(w.w, w.w);
    }
    if (tid < 128) s_bm[tid] = __ldg(&b_mod[kc * 128 + tid]);
    __syncthreads();

    for (int t = 1; t < NT; t++) {
        // ---- wait: chain flags + xproj readiness ----
        if (t > 1) {
            unsigned target = (unsigned)(8 * (t - 1));
            if (tid == 0)  while (ld_acq(&g_arr[2 * kc]) < target) {}
            if (tid == 32) while (ld_acq(&g_arr[2 * kc + 1]) < target) {}
        }
        if (tid == 64) while (ld_acq(&g_xarr[t]) < 16u) {}           // red target ready
        if (tid == 96 && t == 1) while (ld_acq(&g_xarr[0]) < 16u) {} // stage source (t=1)
        __syncthreads();

        // ---- stage: As[k][b] = modrelu(z_{t-1}[kc*128+k][b]) ----
        {
            const float* zsrc = g_z + ((long)(t - 1) * NH + kc * 128) * NB;
            #pragma unroll
            for (int i = 0; i < 8; i++) {
                int f = i * 256 + tid;            // 2048 f4 = 128k x 16
                int k = f >> 4, c = f & 15;
                float4 z = __ldcg((const float4*)(zsrc + (long)k * NB + c * 4));
                float bm = s_bm[k];
                float4 h;
                h.x = modrelu(z.x, bm); h.y = modrelu(z.y, bm);
                h.z = modrelu(z.z, bm); h.w = modrelu(z.w, bm);
                *(float4*)(As + k * 64 + c * 4) = h;
            }
        }
        __syncthreads();

        // ---- GEMM: 64n x 64b x 128k, 3 LDS.128 + 8 FFMA2 per kk ----
        u64 acc[4][2];
        #pragma unroll
        for (int i = 0; i < 4; i++) { acc[i][0] = 0ull; acc[i][1] = 0ull; }

        #pragma unroll 8
        for (int kk = 0; kk < 128; kk++) {
            const ulonglong2 a   = *(const ulonglong2*)(As + kk * 64 + tb * 4);
            const ulonglong2 w01 = *(const ulonglong2*)(Wd + kk * 128 + tn * 8);
            const ulonglong2 w23 = *(const ulonglong2*)(Wd + kk * 128 + tn * 8 + 4);
            FMA2(acc[0][0], a.x, w01.x); FMA2(acc[0][1], a.y, w01.x);
            FMA2(acc[1][0], a.x, w01.y); FMA2(acc[1][1], a.y, w01.y);
            FMA2(acc[2][0], a.x, w23.x); FMA2(acc[2][1], a.y, w23.x);
            FMA2(acc[3][0], a.x, w23.y); FMA2(acc[3][1], a.y, w23.y);
        }

        // ---- red-accumulate into z_t ----
        {
            float* zdst = g_z + ((long)t * NH + nc * 64 + 4 * tn) * NB + 4 * tb;
            #pragma unroll
            for (int j = 0; j < 4; j++)
                red_add_v4(zdst + (long)j * NB,
                           lo32(acc[j][0]), hi32(acc[j][0]),
                           lo32(acc[j][1]), hi32(acc[j][1]));
        }

        // ---- arrive ----
        __syncthreads();
        if (tid == 0) {
            __threadfence();
            atomicAdd(&g_arr[nc], 1u);
        }
    }
}

// ---------------- kernel 3: fc head (R7, unchanged) ----------------
__global__ __launch_bounds__(256) void fc_kernel(
    const float* __restrict__ w_fc, const float* __restrict__ b_fc,
    const float* __restrict__ b_mod, float* __restrict__ out)
{
    __shared__ float As[64][64];   // [k][b] = h_last slab
    __shared__ float Bs[64][64];   // [k][c']
    const int n0 = blockIdx.x * 64;
    const int tid = threadIdx.x;
    const int tx = tid & 15, ty = tid >> 4;
    const float* zlast = g_z + (long)(NT - 1) * NH * NB;
    float acc[4][4] = {};

    for (int s = 0; s < 16; s++) {
        __syncthreads();
        #pragma unroll
        for (int it = 0; it < 4; it++) {
            int f4 = it * 256 + tid;
            int n = s * 64 + (f4 >> 4);
            float4 z = __ldcg((const float4*)zlast + s * 1024 + f4);
            float bm = __ldg(&b_mod[n]);
            float4 h;
            h.x = modrelu(z.x, bm); h.y = modrelu(z.y, bm);
            h.z = modrelu(z.z, bm); h.w = modrelu(z.w, bm);
            ((float4*)As)[f4] = h;
        }
        #pragma unroll
        for (int it = 0; it < 4; it++) {
            int f4 = it * 256 + tid;
            int np = f4 >> 4, k0 = (f4 & 15) * 4;
            int row = n0 + np; if (row >= NC) row = NC - 1;
            float4 w = *(const float4*)(w_fc + (long)row * NH + s * 64 + k0);
            Bs[k0 + 0][np] = w.x; Bs[k0 + 1][np] = w.y;
            Bs[k0 + 2][np] = w.z; Bs[k0 + 3][np] = w.w;
        }
        __syncthreads();
        #pragma unroll 8
        for (int kk = 0; kk < 64; kk++) {
            float4 av = *(const float4*)(&As[kk][ty * 4]);
            float4 bv = *(const float4*)(&Bs[kk][tx * 4]);
            float a[4] = {av.x, av.y, av.z, av.w};
            float b[4] = {bv.x, bv.y, bv.z, bv.w};
            #pragma unroll
            for (int i = 0; i < 4; i++)
                #pragma unroll
                for (int j = 0; j < 4; j++)
                    acc[i][j] += a[i] * b[j];
        }
    }
    #pragma unroll
    for (int i = 0; i < 4; i++) {
        #pragma unroll
        for (int j = 0; j < 4; j++) {
            int c = n0 + tx * 4 + j;
            if (c < NC) out[(long)(ty * 4 + i) * NC + c] = acc[i][j] + __ldg(&b_fc[c]);
        }
    }
}

// ---------------- launch ----------------
extern "C" void kernel_launch(void* const* d_in, const int* in_sizes, int n_in,
                              void* d_out, int out_size)
{
    const float* x     = (const float*)d_in[0];  // [64,1024,256]
    const float* w_ih  = (const float*)d_in[1];  // [1024,256]
    const float* w_hh  = (const float*)d_in[2];  // [1024,1024]
    const float* b_mod = (const float*)d_in[3];  // [1024]
    const float* w_fc  = (const float*)d_in[4];  // [1000,1024]
    const float* b_fc  = (const float*)d_in[5];  // [1000]
    float* out = (float*)d_out;                  // [64,1000]

    cudaFuncSetAttribute(main_kernel, cudaFuncAttributeMaxDynamicSharedMemorySize, 98304);

    init_kernel<<<4, 256>>>();
    xpose_kernel<<<dim3(NT, ND / 64), 256>>>(x);
    wpose_kernel<<<dim3(NH / 64, ND / 64), 256>>>(w_ih);
    main_kernel<<<RCTAS + WORKERS, 256, 98304>>>(w_hh, b_mod);
    fc_kernel<<<(NC + 63) / 64, 256>>>(w_fc, b_fc, b_mod, out);
}

// round 16
// speedup vs baseline: 1.3498x; 1.2474x over previous
#include <cuda_runtime.h>
#include <math.h>

#define NB 64      // batch
#define NT 1024    // seq len
#define ND 256     // input dim
#define NH 1024    // hidden
#define NC 1000    // classes
#define RCTAS 128  // persistent recurrence CTAs (1 CTA/SM resident)
#define FSTRIDE 32 // flag padding: one u32 per 128-byte line

typedef unsigned long long u64;

// ---------------- scratch (device globals) ----------------
// g_z[t] starts as xproj_t (xproj kernel); recurrence red-accumulates
// W_hh*h_{t-1} into slice t. h = modrelu(z) computed on the fly by readers.
__device__ float g_z[NT * NH * NB];          // [t][n][b]  256 MB
__device__ float g_xT[NT * ND * NB];         // [t][d][b]
__device__ float g_wihT[ND * NH];            // [d][n]
__device__ unsigned g_arr[16 * FSTRIDE];     // padded flags: one per 128B line

// ---------------- sync / math primitives ----------------
__device__ __forceinline__ unsigned ld_acq(const unsigned* p) {
    unsigned v;
    asm volatile("ld.global.acquire.gpu.u32 %0, [%1];" : "=r"(v) : "l"(p));
    return v;
}
#define FMA2(d, a, b) asm("fma.rn.f32x2 %0, %1, %2, %0;" : "+l"(d) : "l"(a), "l"(b))
__device__ __forceinline__ float lo32(u64 v) { return __uint_as_float((unsigned)v); }
__device__ __forceinline__ float hi32(u64 v) { return __uint_as_float((unsigned)(v >> 32)); }

__device__ __forceinline__ void red_add_v4(float* p, float v0, float v1, float v2, float v3) {
    asm volatile("red.global.add.v4.f32 [%0], {%1, %2, %3, %4};"
                 :: "l"(p), "f"(v0), "f"(v1), "f"(v2), "f"(v3) : "memory");
}
__device__ __forceinline__ float modrelu(float z, float bm) {
    float a = fabsf(z) + bm;
    return (a > 0.0f) ? copysignf(a, z) : 0.0f;
}

// ---------------- init: reset dataflow counters each launch ----------------
__global__ void init_kernel() {
    int i = blockIdx.x * 256 + threadIdx.x;
    if (i < 16 * FSTRIDE) g_arr[i] = 0u;
}

// ---------------- transpose kernels (R7, unchanged) ----------------
__global__ __launch_bounds__(256) void xpose_kernel(const float* __restrict__ x) {
    __shared__ float T[64][65];
    const int t0 = blockIdx.x;
    const int d0 = blockIdx.y * 64;
    const int tid = threadIdx.x;
    const int b = tid & 63;
    #pragma unroll
    for (int it = 0; it < 4; it++) {
        int d4 = (tid >> 6) * 4 + it * 16;
        float4 v = __ldg((const float4*)(x + (long)b * (NT * ND) + (long)t0 * ND + d0 + d4));
        T[d4 + 0][b] = v.x; T[d4 + 1][b] = v.y;
        T[d4 + 2][b] = v.z; T[d4 + 3][b] = v.w;
    }
    __syncthreads();
    #pragma unroll
    for (int it = 0; it < 4; it++) {
        int dr = it * 16 + (tid >> 4);
        int b4 = (tid & 15) * 4;
        float4 v = make_float4(T[dr][b4], T[dr][b4 + 1], T[dr][b4 + 2], T[dr][b4 + 3]);
        *(float4*)(g_xT + ((long)t0 * ND + d0 + dr) * NB + b4) = v;
    }
}

__global__ __launch_bounds__(256) void wpose_kernel(const float* __restrict__ w_ih) {
    __shared__ float T[64][65];
    const int n0 = blockIdx.x * 64;
    const int d0 = blockIdx.y * 64;
    const int tid = threadIdx.x;
    const int n = tid & 63;
    #pragma unroll
    for (int it = 0; it < 4; it++) {
        int d4 = (tid >> 6) * 4 + it * 16;
        float4 v = __ldg((const float4*)(w_ih + (long)(n0 + n) * ND + d0 + d4));
        T[d4 + 0][n] = v.x; T[d4 + 1][n] = v.y;
        T[d4 + 2][n] = v.z; T[d4 + 3][n] = v.w;
    }
    __syncthreads();
    #pragma unroll
    for (int it = 0; it < 4; it++) {
        int dr = it * 16 + (tid >> 4);
        int n4 = (tid & 15) * 4;
        float4 v = make_float4(T[dr][n4], T[dr][n4 + 1], T[dr][n4 + 2], T[dr][n4 + 3]);
        *(float4*)(g_wihT + (long)(d0 + dr) * NH + n0 + n4) = v;
    }
}

// ---------------- kernel 1: xproj (FFMA2, R7-proven) ----------------
__global__ __launch_bounds__(256) void xproj_kernel() {
    __shared__ float As_dup[64 * 128];   // [k][2b dup]  32 KB
    __shared__ float Bs[64 * 64];        // [k][n]       16 KB

    const int t0 = blockIdx.x;
    const int n0 = blockIdx.y * 64;
    const int tid = threadIdx.x;
    const int tx = tid & 15, ty = tid >> 4;

    u64 acc[4][2];
    #pragma unroll
    for (int i = 0; i < 4; i++) { acc[i][0] = 0ull; acc[i][1] = 0ull; }

    for (int p = 0; p < 4; p++) {
        __syncthreads();
        {
            const float2* xsrc = (const float2*)(g_xT + ((long)t0 * ND + p * 64) * NB);
            float4* Ad4 = (float4*)As_dup;
            #pragma unroll
            for (int it = 0; it < 8; it++) {
                int f2 = it * 256 + tid;
                float2 v = __ldg(&xsrc[f2]);
                Ad4[f2] = make_float4(v.x, v.x, v.y, v.y);
            }
        }
        {
            const float4* wsrc = (const float4*)(g_wihT + (long)(p * 64) * NH + n0);
            #pragma unroll
            for (int it = 0; it < 4; it++) {
                int f4 = it * 256 + tid;
                int k = f4 >> 4, n4 = f4 & 15;
                ((float4*)Bs)[f4] = __ldg(&wsrc[(long)k * (NH / 4) + n4]);
            }
        }
        __syncthreads();

        #pragma unroll 8
        for (int kk = 0; kk < 64; kk++) {
            const ulonglong2 bp  = *(const ulonglong2*)(Bs + kk * 64 + tx * 4);
            const ulonglong2 a01 = *(const ulonglong2*)(As_dup + kk * 128 + ty * 8);
            const ulonglong2 a23 = *(const ulonglong2*)(As_dup + kk * 128 + ty * 8 + 4);
            FMA2(acc[0][0], a01.x, bp.x); FMA2(acc[0][1], a01.x, bp.y);
            FMA2(acc[1][0], a01.y, bp.x); FMA2(acc[1][1], a01.y, bp.y);
            FMA2(acc[2][0], a23.x, bp.x); FMA2(acc[2][1], a23.x, bp.y);
            FMA2(acc[3][0], a23.y, bp.x); FMA2(acc[3][1], a23.y, bp.y);
        }
    }

    #pragma unroll
    for (int j = 0; j < 4; j++) {
        int jp = j >> 1;
        float4 v;
        if (j & 1) v = make_float4(hi32(acc[0][jp]), hi32(acc[1][jp]),
                                   hi32(acc[2][jp]), hi32(acc[3][jp]));
        else       v = make_float4(lo32(acc[0][jp]), lo32(acc[1][jp]),
                                   lo32(acc[2][jp]), lo32(acc[3][jp]));
        *(float4*)(g_z + ((long)t0 * NH + n0 + tx * 4 + j) * NB + ty * 4) = v;
    }
}

// ---------------- kernel 2: persistent recurrence (R13 + padded flags) ----------------
// CTA (nc = cta&15, kc = cta>>4). One-time 64 KB dup-W in smem; per-step h stage
// is a straight 32 KB copy. Microtile 4n x 4b per thread: 3 LDS.128 + 8 FFMA2
// per kk (balanced at 32 cyc/kk).
// Step t: wait flags {2kc,2kc+1} >= 8(t-1) -> stage h chunk -> GEMM -> red.v4 ->
//         fence -> arrive g_arr[nc*FSTRIDE].
__global__ __launch_bounds__(256) void recur_kernel(
    const float* __restrict__ w_hh, const float* __restrict__ b_mod)
{
    extern __shared__ float sm[];
    float* Wd = sm;                       // [128k][128] dup W: Wd[k][2n..2n+1]=(w_n,w_n), 64 KB
    float* As = sm + 128 * 128;           // [128k][64b] natural h, 32 KB
    __shared__ float s_bm[128];

    const int tid = threadIdx.x;
    const int cta = blockIdx.x;
    const int nc = cta & 15;
    const int kc = cta >> 4;
    const int tn = tid >> 4;              // n-quad 0..15  (n = 4tn + j)
    const int tb = tid & 15;              // b-quad 0..15  (b = 4tb .. 4tb+3)

    // ---- one-time: W slice dup into persistent smem ----
    #pragma unroll
    for (int it = 0; it < 8; it++) {
        int f4 = it * 256 + tid;                 // 2048 f4 = 64n x 32 k-quads
        int np = f4 >> 5, k0 = (f4 & 31) * 4;
        float4 w = __ldg((const float4*)(w_hh + (long)(nc * 64 + np) * NH + kc * 128 + k0));
        *(float2*)(Wd + (k0 + 0) * 128 + 2 * np) = make_float2(w.x, w.x);
        *(float2*)(Wd + (k0 + 1) * 128 + 2 * np) = make_float2(w.y, w.y);
        *(float2*)(Wd + (k0 + 2) * 128 + 2 * np) = make_float2(w.z, w.z);
        *(float2*)(Wd + (k0 + 3) * 128 + 2 * np) = make_float2(w.w, w.w);
    }
    if (tid < 128) s_bm[tid] = __ldg(&b_mod[kc * 128 + tid]);
    __syncthreads();

    for (int t = 1; t < NT; t++) {
        // ---- wait: the two column groups covering chunk kc of z_{t-1} ----
        if (t > 1) {
            unsigned target = (unsigned)(8 * (t - 1));
            if (tid == 0)  while (ld_acq(&g_arr[(2 * kc) * FSTRIDE]) < target) {}
            if (tid == 32) while (ld_acq(&g_arr[(2 * kc + 1) * FSTRIDE]) < target) {}
        }
        __syncthreads();

        // ---- stage: As[k][b] = modrelu(z_{t-1}[kc*128+k][b]) — LDGs hoisted (MLP=8) ----
        {
            const float* zsrc = g_z + ((long)(t - 1) * NH + kc * 128) * NB;
            float4 r[8];
            #pragma unroll
            for (int i = 0; i < 8; i++) {
                int f = i * 256 + tid;            // 2048 f4 = 128k x 16
                r[i] = __ldcg((const float4*)(zsrc + (long)(f >> 4) * NB + (f & 15) * 4));
            }
            #pragma unroll
            for (int i = 0; i < 8; i++) {
                int f = i * 256 + tid;
                int k = f >> 4, c = f & 15;
                float bm = s_bm[k];
                float4 h;
                h.x = modrelu(r[i].x, bm); h.y = modrelu(r[i].y, bm);
                h.z = modrelu(r[i].z, bm); h.w = modrelu(r[i].w, bm);
                *(float4*)(As + k * 64 + c * 4) = h;
            }
        }
        __syncthreads();

        // ---- GEMM: 64n x 64b x 128k, 3 LDS.128 + 8 FFMA2 per kk ----
        u64 acc[4][2];
        #pragma unroll
        for (int i = 0; i < 4; i++) { acc[i][0] = 0ull; acc[i][1] = 0ull; }

        #pragma unroll 8
        for (int kk = 0; kk < 128; kk++) {
            const ulonglong2 a   = *(const ulonglong2*)(As + kk * 64 + tb * 4);
            const ulonglong2 w01 = *(const ulonglong2*)(Wd + kk * 128 + tn * 8);
            const ulonglong2 w23 = *(const ulonglong2*)(Wd + kk * 128 + tn * 8 + 4);
            FMA2(acc[0][0], a.x, w01.x); FMA2(acc[0][1], a.y, w01.x);
            FMA2(acc[1][0], a.x, w01.y); FMA2(acc[1][1], a.y, w01.y);
            FMA2(acc[2][0], a.x, w23.x); FMA2(acc[2][1], a.y, w23.x);
            FMA2(acc[3][0], a.x, w23.y); FMA2(acc[3][1], a.y, w23.y);
        }

        // ---- red-accumulate into z_t: rows n = nc*64 + 4tn + j, batch 4tb..4tb+3 ----
        {
            float* zdst = g_z + ((long)t * NH + nc * 64 + 4 * tn) * NB + 4 * tb;
            #pragma unroll
            for (int j = 0; j < 4; j++)
                red_add_v4(zdst + (long)j * NB,
                           lo32(acc[j][0]), hi32(acc[j][0]),
                           lo32(acc[j][1]), hi32(acc[j][1]));
        }

        // ---- arrive ----
        __syncthreads();
        if (tid == 0) {
            __threadfence();
            atomicAdd(&g_arr[nc * FSTRIDE], 1u);
        }
    }
}

// ---------------- kernel 3: fc head (R7, unchanged) ----------------
__global__ __launch_bounds__(256) void fc_kernel(
    const float* __restrict__ w_fc, const float* __restrict__ b_fc,
    const float* __restrict__ b_mod, float* __restrict__ out)
{
    __shared__ float As[64][64];   // [k][b] = h_last slab
    __shared__ float Bs[64][64];   // [k][c']
    const int n0 = blockIdx.x * 64;
    const int tid = threadIdx.x;
    const int tx = tid & 15, ty = tid >> 4;
    const float* zlast = g_z + (long)(NT - 1) * NH * NB;
    float acc[4][4] = {};

    for (int s = 0; s < 16; s++) {
        __syncthreads();
        #pragma unroll
        for (int it = 0; it < 4; it++) {
            int f4 = it * 256 + tid;
            int n = s * 64 + (f4 >> 4);
            float4 z = __ldcg((const float4*)zlast + s * 1024 + f4);
            float bm = __ldg(&b_mod[n]);
            float4 h;
            h.x = modrelu(z.x, bm); h.y = modrelu(z.y, bm);
            h.z = modrelu(z.z, bm); h.w = modrelu(z.w, bm);
            ((float4*)As)[f4] = h;
        }
        #pragma unroll
        for (int it = 0; it < 4; it++) {
            int f4 = it * 256 + tid;
            int np = f4 >> 4, k0 = (f4 & 15) * 4;
            int row = n0 + np; if (row >= NC) row = NC - 1;
            float4 w = *(const float4*)(w_fc + (long)row * NH + s * 64 + k0);
            Bs[k0 + 0][np] = w.x; Bs[k0 + 1][np] = w.y;
            Bs[k0 + 2][np] = w.z; Bs[k0 + 3][np] = w.w;
        }
        __syncthreads();
        #pragma unroll 8
        for (int kk = 0; kk < 64; kk++) {
            float4 av = *(const float4*)(&As[kk][ty * 4]);
            float4 bv = *(const float4*)(&Bs[kk][tx * 4]);
            float a[4] = {av.x, av.y, av.z, av.w};
            float b[4] = {bv.x, bv.y, bv.z, bv.w};
            #pragma unroll
            for (int i = 0; i < 4; i++)
                #pragma unroll
                for (int j = 0; j < 4; j++)
                    acc[i][j] += a[i] * b[j];
        }
    }
    #pragma unroll
    for (int i = 0; i < 4; i++) {
        #pragma unroll
        for (int j = 0; j < 4; j++) {
            int c = n0 + tx * 4 + j;
            if (c < NC) out[(long)(ty * 4 + i) * NC + c] = acc[i][j] + __ldg(&b_fc[c]);
        }
    }
}

// ---------------- launch ----------------
extern "C" void kernel_launch(void* const* d_in, const int* in_sizes, int n_in,
                              void* d_out, int out_size)
{
    const float* x     = (const float*)d_in[0];  // [64,1024,256]
    const float* w_ih  = (const float*)d_in[1];  // [1024,256]
    const float* w_hh  = (const float*)d_in[2];  // [1024,1024]
    const float* b_mod = (const float*)d_in[3];  // [1024]
    const float* w_fc  = (const float*)d_in[4];  // [1000,1024]
    const float* b_fc  = (const float*)d_in[5];  // [1000]
    float* out = (float*)d_out;                  // [64,1000]

    cudaFuncSetAttribute(recur_kernel, cudaFuncAttributeMaxDynamicSharedMemorySize, 98304);

    init_kernel<<<2, 256>>>();
    xpose_kernel<<<dim3(NT, ND / 64), 256>>>(x);
    wpose_kernel<<<dim3(NH / 64, ND / 64), 256>>>(w_ih);
    xproj_kernel<<<dim3(NT, NH / 64), 256>>>();
    recur_kernel<<<RCTAS, 256, 98304>>>(w_hh, b_mod);
    fc_kernel<<<(NC + 63) / 64, 256>>>(w_fc, b_fc, b_mod, out);
}

// round 17
// speedup vs baseline: 1.3601x; 1.0077x over previous
#include <cuda_runtime.h>
#include <math.h>

#define NB 64      // batch
#define NT 1024    // seq len
#define ND 256     // input dim
#define NH 1024    // hidden
#define NC 1000    // classes
#define RCTAS 128  // persistent recurrence CTAs (1 CTA/SM resident)

typedef unsigned long long u64;

// ---------------- scratch (device globals) ----------------
// g_z[t] starts as xproj_t (xproj kernel); recurrence red-accumulates
// W_hh*h_{t-1} into slice t. h = modrelu(z) computed on the fly by readers.
__device__ float g_z[NT * NH * NB];        // [t][n][b]  256 MB
__device__ float g_xT[NT * ND * NB];       // [t][d][b]
__device__ float g_wihT[ND * NH];          // [d][n]
__device__ unsigned g_arr[16];             // per n-group(64) arrival counters

// ---------------- sync / math primitives ----------------
__device__ __forceinline__ unsigned ld_acq(const unsigned* p) {
    unsigned v;
    asm volatile("ld.global.acquire.gpu.u32 %0, [%1];" : "=r"(v) : "l"(p));
    return v;
}
#define FMA2(d, a, b) asm("fma.rn.f32x2 %0, %1, %2, %0;" : "+l"(d) : "l"(a), "l"(b))
__device__ __forceinline__ float lo32(u64 v) { return __uint_as_float((unsigned)v); }
__device__ __forceinline__ float hi32(u64 v) { return __uint_as_float((unsigned)(v >> 32)); }

__device__ __forceinline__ void red_add_v4(float* p, float v0, float v1, float v2, float v3) {
    asm volatile("red.global.add.v4.f32 [%0], {%1, %2, %3, %4};"
                 :: "l"(p), "f"(v0), "f"(v1), "f"(v2), "f"(v3) : "memory");
}
__device__ __forceinline__ float modrelu(float z, float bm) {
    float a = fabsf(z) + bm;
    return (a > 0.0f) ? copysignf(a, z) : 0.0f;
}

// ---------------- init: reset dataflow counters each launch ----------------
__global__ void init_kernel() {
    if (threadIdx.x < 16) g_arr[threadIdx.x] = 0u;
}

// ---------------- transpose kernels (R7, unchanged) ----------------
__global__ __launch_bounds__(256) void xpose_kernel(const float* __restrict__ x) {
    __shared__ float T[64][65];
    const int t0 = blockIdx.x;
    const int d0 = blockIdx.y * 64;
    const int tid = threadIdx.x;
    const int b = tid & 63;
    #pragma unroll
    for (int it = 0; it < 4; it++) {
        int d4 = (tid >> 6) * 4 + it * 16;
        float4 v = __ldg((const float4*)(x + (long)b * (NT * ND) + (long)t0 * ND + d0 + d4));
        T[d4 + 0][b] = v.x; T[d4 + 1][b] = v.y;
        T[d4 + 2][b] = v.z; T[d4 + 3][b] = v.w;
    }
    __syncthreads();
    #pragma unroll
    for (int it = 0; it < 4; it++) {
        int dr = it * 16 + (tid >> 4);
        int b4 = (tid & 15) * 4;
        float4 v = make_float4(T[dr][b4], T[dr][b4 + 1], T[dr][b4 + 2], T[dr][b4 + 3]);
        *(float4*)(g_xT + ((long)t0 * ND + d0 + dr) * NB + b4) = v;
    }
}

__global__ __launch_bounds__(256) void wpose_kernel(const float* __restrict__ w_ih) {
    __shared__ float T[64][65];
    const int n0 = blockIdx.x * 64;
    const int d0 = blockIdx.y * 64;
    const int tid = threadIdx.x;
    const int n = tid & 63;
    #pragma unroll
    for (int it = 0; it < 4; it++) {
        int d4 = (tid >> 6) * 4 + it * 16;
        float4 v = __ldg((const float4*)(w_ih + (long)(n0 + n) * ND + d0 + d4));
        T[d4 + 0][n] = v.x; T[d4 + 1][n] = v.y;
        T[d4 + 2][n] = v.z; T[d4 + 3][n] = v.w;
    }
    __syncthreads();
    #pragma unroll
    for (int it = 0; it < 4; it++) {
        int dr = it * 16 + (tid >> 4);
        int n4 = (tid & 15) * 4;
        float4 v = make_float4(T[dr][n4], T[dr][n4 + 1], T[dr][n4 + 2], T[dr][n4 + 3]);
        *(float4*)(g_wihT + (long)(d0 + dr) * NH + n0 + n4) = v;
    }
}

// ---------------- kernel 1: xproj — 24 KB smem, 4 CTAs/SM ----------------
// xprojT[t0][n0+n][b] = sum_d xT[t0][d][b] * wihT[d][n0+n], 8 passes of k=32.
// Layout = R13-proven: natural A [32k][64b], dup W [32k][128]; microtile 4n x 4b.
__global__ __launch_bounds__(256, 4) void xproj_kernel() {
    __shared__ float As[32 * 64];     // 8 KB   [k][b]
    __shared__ float Wd[32 * 128];    // 16 KB  [k][2n dup]

    const int t0 = blockIdx.x;
    const int n0 = blockIdx.y * 64;
    const int tid = threadIdx.x;
    const int tn = tid >> 4;          // n-quad 0..15 (n = 4tn + j)
    const int tb = tid & 15;          // b-quad 0..15 (b = 4tb .. 4tb+3)

    u64 acc[4][2];
    #pragma unroll
    for (int i = 0; i < 4; i++) { acc[i][0] = 0ull; acc[i][1] = 0ull; }

    for (int p = 0; p < 8; p++) {
        __syncthreads();
        // stage A: straight f4 copy (512 f4 = 32k x 16)
        {
            const float4* xs = (const float4*)(g_xT + ((long)t0 * ND + p * 32) * NB);
            #pragma unroll
            for (int i = 0; i < 2; i++) {
                int f = i * 256 + tid;
                ((float4*)As)[f] = __ldg(&xs[f]);
            }
        }
        // stage W dup: 512 f4 source = 32k x 16 n-quads
        {
            #pragma unroll
            for (int i = 0; i < 2; i++) {
                int f = i * 256 + tid;
                int k = f >> 4, nq = (f & 15) * 4;
                float4 w = __ldg((const float4*)(g_wihT + (long)(p * 32 + k) * NH + n0 + nq));
                *(float2*)(Wd + k * 128 + 2 * (nq + 0)) = make_float2(w.x, w.x);
                *(float2*)(Wd + k * 128 + 2 * (nq + 1)) = make_float2(w.y, w.y);
                *(float2*)(Wd + k * 128 + 2 * (nq + 2)) = make_float2(w.z, w.z);
                *(float2*)(Wd + k * 128 + 2 * (nq + 3)) = make_float2(w.w, w.w);
            }
        }
        __syncthreads();

        #pragma unroll
        for (int kk = 0; kk < 32; kk++) {
            const ulonglong2 a   = *(const ulonglong2*)(As + kk * 64 + tb * 4);
            const ulonglong2 w01 = *(const ulonglong2*)(Wd + kk * 128 + tn * 8);
            const ulonglong2 w23 = *(const ulonglong2*)(Wd + kk * 128 + tn * 8 + 4);
            FMA2(acc[0][0], a.x, w01.x); FMA2(acc[0][1], a.y, w01.x);
            FMA2(acc[1][0], a.x, w01.y); FMA2(acc[1][1], a.y, w01.y);
            FMA2(acc[2][0], a.x, w23.x); FMA2(acc[2][1], a.y, w23.x);
            FMA2(acc[3][0], a.x, w23.y); FMA2(acc[3][1], a.y, w23.y);
        }
    }

    // store: z[t0][n0 + 4tn + j][4tb .. 4tb+3]
    float* zdst = g_z + ((long)t0 * NH + n0 + 4 * tn) * NB + 4 * tb;
    #pragma unroll
    for (int j = 0; j < 4; j++) {
        float4 v = make_float4(lo32(acc[j][0]), hi32(acc[j][0]),
                               lo32(acc[j][1]), hi32(acc[j][1]));
        *(float4*)(zdst + (long)j * NB) = v;
    }
}

// ---------------- kernel 2: persistent recurrence (R13 exact, proven 7746us) ----------------
__global__ __launch_bounds__(256) void recur_kernel(
    const float* __restrict__ w_hh, const float* __restrict__ b_mod)
{
    extern __shared__ float sm[];
    float* Wd = sm;                       // [128k][128] dup W, 64 KB
    float* As = sm + 128 * 128;           // [128k][64b] natural h, 32 KB
    __shared__ float s_bm[128];

    const int tid = threadIdx.x;
    const int cta = blockIdx.x;
    const int nc = cta & 15;
    const int kc = cta >> 4;
    const int tn = tid >> 4;              // n-quad 0..15
    const int tb = tid & 15;              // b-quad 0..15

    // ---- one-time: W slice dup into persistent smem ----
    #pragma unroll
    for (int it = 0; it < 8; it++) {
        int f4 = it * 256 + tid;                 // 2048 f4 = 64n x 32 k-quads
        int np = f4 >> 5, k0 = (f4 & 31) * 4;
        float4 w = __ldg((const float4*)(w_hh + (long)(nc * 64 + np) * NH + kc * 128 + k0));
        *(float2*)(Wd + (k0 + 0) * 128 + 2 * np) = make_float2(w.x, w.x);
        *(float2*)(Wd + (k0 + 1) * 128 + 2 * np) = make_float2(w.y, w.y);
        *(float2*)(Wd + (k0 + 2) * 128 + 2 * np) = make_float2(w.z, w.z);
        *(float2*)(Wd + (k0 + 3) * 128 + 2 * np) = make_float2(w.w, w.w);
    }
    if (tid < 128) s_bm[tid] = __ldg(&b_mod[kc * 128 + tid]);
    __syncthreads();

    for (int t = 1; t < NT; t++) {
        // ---- wait: the two column groups covering chunk kc of z_{t-1} ----
        if (t > 1) {
            unsigned target = (unsigned)(8 * (t - 1));
            if (tid == 0)  while (ld_acq(&g_arr[2 * kc]) < target) {}
            if (tid == 32) while (ld_acq(&g_arr[2 * kc + 1]) < target) {}
        }
        __syncthreads();

        // ---- stage: As[k][b] = modrelu(z_{t-1}[kc*128+k][b]) — straight 32 KB copy ----
        {
            const float* zsrc = g_z + ((long)(t - 1) * NH + kc * 128) * NB;
            #pragma unroll
            for (int i = 0; i < 8; i++) {
                int f = i * 256 + tid;            // 2048 f4 = 128k x 16
                int k = f >> 4, c = f & 15;
                float4 z = __ldcg((const float4*)(zsrc + (long)k * NB + c * 4));
                float bm = s_bm[k];
                float4 h;
                h.x = modrelu(z.x, bm); h.y = modrelu(z.y, bm);
                h.z = modrelu(z.z, bm); h.w = modrelu(z.w, bm);
                *(float4*)(As + k * 64 + c * 4) = h;
            }
        }
        __syncthreads();

        // ---- GEMM: 64n x 64b x 128k, 3 LDS.128 + 8 FFMA2 per kk ----
        u64 acc[4][2];
        #pragma unroll
        for (int i = 0; i < 4; i++) { acc[i][0] = 0ull; acc[i][1] = 0ull; }

        #pragma unroll 8
        for (int kk = 0; kk < 128; kk++) {
            const ulonglong2 a   = *(const ulonglong2*)(As + kk * 64 + tb * 4);
            const ulonglong2 w01 = *(const ulonglong2*)(Wd + kk * 128 + tn * 8);
            const ulonglong2 w23 = *(const ulonglong2*)(Wd + kk * 128 + tn * 8 + 4);
            FMA2(acc[0][0], a.x, w01.x); FMA2(acc[0][1], a.y, w01.x);
            FMA2(acc[1][0], a.x, w01.y); FMA2(acc[1][1], a.y, w01.y);
            FMA2(acc[2][0], a.x, w23.x); FMA2(acc[2][1], a.y, w23.x);
            FMA2(acc[3][0], a.x, w23.y); FMA2(acc[3][1], a.y, w23.y);
        }

        // ---- red-accumulate into z_t: rows n = nc*64 + 4tn + j, batch 4tb..4tb+3 ----
        {
            float* zdst = g_z + ((long)t * NH + nc * 64 + 4 * tn) * NB + 4 * tb;
            #pragma unroll
            for (int j = 0; j < 4; j++)
                red_add_v4(zdst + (long)j * NB,
                           lo32(acc[j][0]), hi32(acc[j][0]),
                           lo32(acc[j][1]), hi32(acc[j][1]));
        }

        // ---- arrive ----
        __syncthreads();
        if (tid == 0) {
            __threadfence();
            atomicAdd(&g_arr[nc], 1u);
        }
    }
}

// ---------------- kernel 3: fc head (R7, unchanged) ----------------
__global__ __launch_bounds__(256) void fc_kernel(
    const float* __restrict__ w_fc, const float* __restrict__ b_fc,
    const float* __restrict__ b_mod, float* __restrict__ out)
{
    __shared__ float As[64][64];   // [k][b] = h_last slab
    __shared__ float Bs[64][64];   // [k][c']
    const int n0 = blockIdx.x * 64;
    const int tid = threadIdx.x;
    const int tx = tid & 15, ty = tid >> 4;
    const float* zlast = g_z + (long)(NT - 1) * NH * NB;
    float acc[4][4] = {};

    for (int s = 0; s < 16; s++) {
        __syncthreads();
        #pragma unroll
        for (int it = 0; it < 4; it++) {
            int f4 = it * 256 + tid;
            int n = s * 64 + (f4 >> 4);
            float4 z = __ldcg((const float4*)zlast + s * 1024 + f4);
            float bm = __ldg(&b_mod[n]);
            float4 h;
            h.x = modrelu(z.x, bm); h.y = modrelu(z.y, bm);
            h.z = modrelu(z.z, bm); h.w = modrelu(z.w, bm);
            ((float4*)As)[f4] = h;
        }
        #pragma unroll
        for (int it = 0; it < 4; it++) {
            int f4 = it * 256 + tid;
            int np = f4 >> 4, k0 = (f4 & 15) * 4;
            int row = n0 + np; if (row >= NC) row = NC - 1;
            float4 w = *(const float4*)(w_fc + (long)row * NH + s * 64 + k0);
            Bs[k0 + 0][np] = w.x; Bs[k0 + 1][np] = w.y;
            Bs[k0 + 2][np] = w.z; Bs[k0 + 3][np] = w.w;
        }
        __syncthreads();
        #pragma unroll 8
        for (int kk = 0; kk < 64; kk++) {
            float4 av = *(const float4*)(&As[kk][ty * 4]);
            float4 bv = *(const float4*)(&Bs[kk][tx * 4]);
            float a[4] = {av.x, av.y, av.z, av.w};
            float b[4] = {bv.x, bv.y, bv.z, bv.w};
            #pragma unroll
            for (int i = 0; i < 4; i++)
                #pragma unroll
                for (int j = 0; j < 4; j++)
                    acc[i][j] += a[i] * b[j];
        }
    }
    #pragma unroll
    for (int i = 0; i < 4; i++) {
        #pragma unroll
        for (int j = 0; j < 4; j++) {
            int c = n0 + tx * 4 + j;
            if (c < NC) out[(long)(ty * 4 + i) * NC + c] = acc[i][j] + __ldg(&b_fc[c]);
        }
    }
}

// ---------------- launch ----------------
extern "C" void kernel_launch(void* const* d_in, const int* in_sizes, int n_in,
                              void* d_out, int out_size)
{
    const float* x     = (const float*)d_in[0];  // [64,1024,256]
    const float* w_ih  = (const float*)d_in[1];  // [1024,256]
    const float* w_hh  = (const float*)d_in[2];  // [1024,1024]
    const float* b_mod = (const float*)d_in[3];  // [1024]
    const float* w_fc  = (const float*)d_in[4];  // [1000,1024]
    const float* b_fc  = (const float*)d_in[5];  // [1000]
    float* out = (float*)d_out;                  // [64,1000]

    cudaFuncSetAttribute(recur_kernel, cudaFuncAttributeMaxDynamicSharedMemorySize, 98304);

    init_kernel<<<1, 32>>>();
    xpose_kernel<<<dim3(NT, ND / 64), 256>>>(x);
    wpose_kernel<<<dim3(NH / 64, ND / 64), 256>>>(w_ih);
    xproj_kernel<<<dim3(NT, NH / 64), 256>>>();
    recur_kernel<<<RCTAS, 256, 98304>>>(w_hh, b_mod);
    fc_kernel<<<(NC + 63) / 64, 256>>>(w_fc, b_fc, b_mod, out);
}